// round 9
// baseline (speedup 1.0000x reference)
#include <cuda_runtime.h>
#include <cuda_fp16.h>
#include <cstdint>
#include <math.h>

#define IN_DIM  1024
#define OUT_DIM 1024
#define NE      8
#define NTOK    8192
#define KTOT    (NE * IN_DIM)          // 8192
#define BM      128
#define BN      128
#define NCHUNK  257                     // 256 weight chunks (K=32) + 1 gate/bias chunk
#define STAGES  5

// SMEM per stage (bytes)
#define SA_STAGE 8192                   // A: 16 m8-blocks x 4 k8-blocks x 128B
#define SB_STAGE 8192                   // B: 32 k-rows x 256B (swizzled 16B cols)
#define SB_BASE  (STAGES * SA_STAGE)                      // 40960
#define SG_BASE  (SB_BASE + STAGES * SB_STAGE)            // 81920
#define SMEM_BYTES (SG_BASE + BM * NE * 4)                // 86016

// ---------------- scratch ----------------
__device__ float  g_gates[NTOK * NE];                // softmax gates [N, E]
__device__ __half g_Wh[KTOT * OUT_DIM];              // fp16 We, [K, O] row-major, 16 MB

// ---------------- helpers ----------------
__device__ __forceinline__ uint32_t smem_u32(const void* p) {
    uint32_t a;
    asm("{ .reg .u64 t; cvta.to.shared.u64 t, %1; cvt.u32.u64 %0, t; }" : "=r"(a) : "l"(p));
    return a;
}
__device__ __forceinline__ uint32_t packh2(float lo, float hi) {
    uint32_t r;
    asm("cvt.rn.f16x2.f32 %0, %1, %2;" : "=r"(r) : "f"(hi), "f"(lo));
    return r;
}
// swizzled byte offset of 16B col-slot `col16` in k-row `kr` of a B stage
__device__ __forceinline__ uint32_t bswz(int kr, int col16) {
    return (uint32_t)(kr * 256 + ((((col16 ^ kr) & 7) | (col16 & 8)) << 4));
}

// ---------------- kernel 1: gating softmax (32 tokens / 1024-thread block) ----------------
__global__ __launch_bounds__(1024) void gate_kernel(const float* __restrict__ x,
                                                    const float* __restrict__ Wg,
                                                    const float* __restrict__ bg) {
    __shared__ float sW[NE * IN_DIM];   // transposed: sW[e*1024 + i]
    int tid = threadIdx.x;
    for (int idx = tid; idx < NE * IN_DIM; idx += 1024) {
        int i = idx >> 3, e = idx & 7;
        sW[e * IN_DIM + i] = Wg[idx];
    }
    __syncthreads();
    int w = tid >> 5, lane = tid & 31;
    int n = blockIdx.x * 32 + w;
    float acc[NE];
#pragma unroll
    for (int e = 0; e < NE; e++) acc[e] = 0.f;
    const float* xr = x + (size_t)n * IN_DIM;
    for (int i = lane; i < IN_DIM; i += 32) {
        float xv = xr[i];
#pragma unroll
        for (int e = 0; e < NE; e++) acc[e] += xv * sW[e * IN_DIM + i];
    }
#pragma unroll
    for (int e = 0; e < NE; e++) {
#pragma unroll
        for (int off = 16; off; off >>= 1)
            acc[e] += __shfl_xor_sync(0xffffffffu, acc[e], off);
    }
    if (lane == 0) {
        float v[NE], m = -1e30f;
#pragma unroll
        for (int e = 0; e < NE; e++) { v[e] = acc[e] + bg[e]; m = fmaxf(m, v[e]); }
        float s = 0.f;
#pragma unroll
        for (int e = 0; e < NE; e++) { v[e] = expf(v[e] - m); s += v[e]; }
        float inv = 1.0f / s;
#pragma unroll
        for (int e = 0; e < NE; e++) g_gates[n * NE + e] = v[e] * inv;
    }
}

// ---------------- kernel 2: We fp32 -> fp16 copy (layout preserved) ----------------
__global__ __launch_bounds__(256) void convert_kernel(const float* __restrict__ We) {
    int total = KTOT * OUT_DIM / 8;
    for (int idx = blockIdx.x * blockDim.x + threadIdx.x; idx < total;
         idx += gridDim.x * blockDim.x) {
        const float4* s = (const float4*)We + (size_t)idx * 2;
        float4 a = s[0], b = s[1];
        uint4 w;
        w.x = packh2(a.x, a.y); w.y = packh2(a.z, a.w);
        w.z = packh2(b.x, b.y); w.w = packh2(b.z, b.w);
        *(uint4*)(g_Wh + (size_t)idx * 8) = w;
    }
}

// ---------------- kernel 3: fused fp16 mma GEMM, 4 warps x (64x64) warp tiles ----------------
__global__ __launch_bounds__(128, 2) void moe_mma_kernel(const float* __restrict__ x,
                                                         const float* __restrict__ be,
                                                         float* __restrict__ out) {
    extern __shared__ __align__(16) char smem[];
    const uint32_t aBase = smem_u32(smem);
    const uint32_t bBase = aBase + SB_BASE;
    float* sg = (float*)(smem + SG_BASE);

    int tid = threadIdx.x;
    int m0 = blockIdx.y * BM, o0 = blockIdx.x * BN;

    for (int i = tid; i < BM * NE; i += 128) sg[i] = g_gates[m0 * NE + i];
    __syncthreads();

    // ---- A producer mapping: 1 thread per row, 4 k8-quads each ----
    const int row = tid;
    const int m8p = row >> 3, r8p = row & 7;
    uint32_t aoffQ[4];
#pragma unroll
    for (int q = 0; q < 4; q++)
        aoffQ[q] = (uint32_t)(((m8p * 4 + q) * 128) + (((r8p + 4 * q) & 7) * 16));
    const float* xrow = x + (size_t)(m0 + row) * IN_DIM;

    // ---- B producer mapping: 4 threads per k-row, 4 x 16B slots each ----
    const int kr = tid >> 2, segB = tid & 3;
    uint32_t bd[4];
#pragma unroll
    for (int j = 0; j < 4; j++) bd[j] = bswz(kr, segB + 4 * j);

    auto produceB = [&](int st, int c) {
        uint32_t sbase = bBase + (uint32_t)st * SB_STAGE;
        if (c < 256) {
            int ic = c >> 3, e = c & 7;
            const __half* src = g_Wh + (size_t)(e * 1024 + ic * 32 + kr) * OUT_DIM + o0 + segB * 8;
#pragma unroll
            for (int j = 0; j < 4; j++)
                asm volatile("cp.async.cg.shared.global [%0], [%1], 16;"
                             :: "r"(sbase + bd[j]), "l"(src + 32 * j));
        } else {
            if (kr < 8) {
                const float* s0 = be + (size_t)kr * OUT_DIM + o0 + segB * 8;
#pragma unroll
                for (int j = 0; j < 4; j++) {
                    float4 a = *(const float4*)(s0 + 32 * j);
                    float4 b = *(const float4*)(s0 + 32 * j + 4);
                    asm volatile("st.shared.v4.b32 [%0], {%1,%2,%3,%4};" :: "r"(sbase + bd[j]),
                                 "r"(packh2(a.x, a.y)), "r"(packh2(a.z, a.w)),
                                 "r"(packh2(b.x, b.y)), "r"(packh2(b.z, b.w)));
                }
            } else {
#pragma unroll
                for (int j = 0; j < 4; j++)
                    asm volatile("st.shared.v4.b32 [%0], {%1,%1,%1,%1};" :: "r"(sbase + bd[j]), "r"(0u));
            }
        }
        asm volatile("cp.async.commit_group;");
    };
    auto produceA = [&](int st, int c) {
        uint32_t base = aBase + (uint32_t)st * SA_STAGE;
        if (c < 256) {
            int ic = c >> 3, e = c & 7;
            float ge = sg[row * NE + e];
#pragma unroll
            for (int q = 0; q < 4; q++) {
                const float* p = xrow + ic * 32 + q * 8;
                float4 v0 = *(const float4*)p, v1 = *(const float4*)(p + 4);
                asm volatile("st.shared.v4.b32 [%0], {%1,%2,%3,%4};" :: "r"(base + aoffQ[q]),
                             "r"(packh2(v0.x * ge, v0.y * ge)), "r"(packh2(v0.z * ge, v0.w * ge)),
                             "r"(packh2(v1.x * ge, v1.y * ge)), "r"(packh2(v1.z * ge, v1.w * ge)));
            }
        } else {
            const float* g = &sg[row * NE];
            asm volatile("st.shared.v4.b32 [%0], {%1,%2,%3,%4};" :: "r"(base + aoffQ[0]),
                         "r"(packh2(g[0], g[1])), "r"(packh2(g[2], g[3])),
                         "r"(packh2(g[4], g[5])), "r"(packh2(g[6], g[7])));
#pragma unroll
            for (int q = 1; q < 4; q++)
                asm volatile("st.shared.v4.b32 [%0], {%1,%1,%1,%1};" :: "r"(base + aoffQ[q]), "r"(0u));
        }
    };

    // ---- accumulators / warp mapping (2x2 warps, 64x64 per warp) ----
    float acc[4][8][4];
#pragma unroll
    for (int mi = 0; mi < 4; mi++)
#pragma unroll
        for (int ni = 0; ni < 8; ni++)
#pragma unroll
            for (int q = 0; q < 4; q++) acc[mi][ni][q] = 0.f;

    int wid = tid >> 5, lane = tid & 31;
    int wm = (wid & 1) * 64, wn = (wid >> 1) * 64;
    int lr = lane >> 2, lc = lane & 3;
    const int wmBlk = (wid & 1) * 8;
    const int wn8 = (wid >> 1) * 8;

    // A ldmatrix lane constant
    const int jm = (lane >> 3) & 1, jk = lane >> 4, rr = lane & 7;
    const uint32_t aLane = (uint32_t)((jm * 4 + jk) * 128 + (((rr + 4 * jk) & 7) * 16));
    // B ldmatrix.trans lane constants
    const int jb = lane >> 3, rb = lane & 7;
    const int kb = 8 * (jb & 1) + rb;
    const int nb = jb >> 1;

    auto compute = [&](int st) {
        const uint32_t A = aBase + (uint32_t)st * SA_STAGE + aLane;
        const uint32_t B = bBase + (uint32_t)st * SB_STAGE;
#pragma unroll
        for (int ks = 0; ks < 2; ks++) {
            uint32_t bf[8][2];
#pragma unroll
            for (int p = 0; p < 4; p++) {
                int krL = 16 * ks + kb;
                int col16 = wn8 + 2 * p + nb;
                uint32_t addr = B + bswz(krL, col16);
                asm volatile("ldmatrix.sync.aligned.m8n8.x4.trans.shared.b16 {%0,%1,%2,%3}, [%4];"
                             : "=r"(bf[2 * p][0]), "=r"(bf[2 * p][1]),
                               "=r"(bf[2 * p + 1][0]), "=r"(bf[2 * p + 1][1])
                             : "r"(addr));
            }
#pragma unroll
            for (int mi = 0; mi < 4; mi++) {
                uint32_t a0, a1, a2, a3;
                uint32_t addr = A + (uint32_t)((((wmBlk + 2 * mi) * 4) + 2 * ks) * 128);
                asm volatile("ldmatrix.sync.aligned.m8n8.x4.shared.b16 {%0,%1,%2,%3}, [%4];"
                             : "=r"(a0), "=r"(a1), "=r"(a2), "=r"(a3) : "r"(addr));
#pragma unroll
                for (int ni = 0; ni < 8; ni++)
                    asm volatile(
                        "mma.sync.aligned.m16n8k16.row.col.f32.f16.f16.f32 "
                        "{%0,%1,%2,%3}, {%4,%5,%6,%7}, {%8,%9}, {%0,%1,%2,%3};"
                        : "+f"(acc[mi][ni][0]), "+f"(acc[mi][ni][1]),
                          "+f"(acc[mi][ni][2]), "+f"(acc[mi][ni][3])
                        : "r"(a0), "r"(a1), "r"(a2), "r"(a3),
                          "r"(bf[ni][0]), "r"(bf[ni][1]));
            }
        }
    };

    // ---- prologue: fill stages 0..3 ----
#pragma unroll
    for (int s = 0; s < STAGES - 1; s++) {
        produceA(s, s);
        produceB(s, s);
    }

    // ---- main loop: c = 0..252, produce chunk c+4 ----
    int st_c = 0, st_p = STAGES - 1;
#pragma unroll 1
    for (int c = 0; c < NCHUNK - STAGES + 1; c++) {
        asm volatile("cp.async.wait_group %0;" :: "n"(STAGES - 2) : "memory");
        __syncthreads();
        produceA(st_p, c + STAGES - 1);
        produceB(st_p, c + STAGES - 1);
        compute(st_c);
        st_c = (st_c == STAGES - 1) ? 0 : st_c + 1;
        st_p = (st_p == STAGES - 1) ? 0 : st_p + 1;
    }
    // ---- tail: last STAGES-1 chunks resident ----
    asm volatile("cp.async.wait_group 0;" ::: "memory");
    __syncthreads();
#pragma unroll
    for (int t = 0; t < STAGES - 1; t++) {
        compute(st_c);
        st_c = (st_c == STAGES - 1) ? 0 : st_c + 1;
    }

    // ---- epilogue: pure store (bias folded into GEMM) ----
#pragma unroll
    for (int mi = 0; mi < 4; mi++) {
        int r = m0 + wm + mi * 16 + lr;
#pragma unroll
        for (int ni = 0; ni < 8; ni++) {
            int cc = o0 + wn + ni * 8 + lc * 2;
            *(float2*)(out + (size_t)r * OUT_DIM + cc) =
                make_float2(acc[mi][ni][0], acc[mi][ni][1]);
            *(float2*)(out + (size_t)(r + 8) * OUT_DIM + cc) =
                make_float2(acc[mi][ni][2], acc[mi][ni][3]);
        }
    }
}

// ---------------- launch ----------------
extern "C" void kernel_launch(void* const* d_in, const int* in_sizes, int n_in,
                              void* d_out, int out_size) {
    const float* x  = (const float*)d_in[0];
    const float* We = (const float*)d_in[1];
    const float* be = (const float*)d_in[2];
    const float* Wg = (const float*)d_in[3];
    const float* bg = (const float*)d_in[4];
    float* out = (float*)d_out;

    cudaFuncSetAttribute(moe_mma_kernel, cudaFuncAttributeMaxDynamicSharedMemorySize, SMEM_BYTES);

    gate_kernel<<<NTOK / 32, 1024>>>(x, Wg, bg);
    convert_kernel<<<2048, 256>>>(We);
    moe_mma_kernel<<<dim3(OUT_DIM / BN, NTOK / BM), 128, SMEM_BYTES>>>(x, be, out);
}

// round 10
// speedup vs baseline: 1.6977x; 1.6977x over previous
#include <cuda_runtime.h>
#include <cuda_fp16.h>
#include <cstdint>
#include <math.h>

#define IN_DIM  1024
#define OUT_DIM 1024
#define NE      8
#define NTOK    8192
#define KTOT    (NE * IN_DIM)          // 8192
#define BM      128
#define BN      256
#define NCHUNK  257                     // 256 weight chunks (K=32) + 1 gate/bias chunk
#define STAGES  4

// SMEM per stage (bytes)
#define SA_STAGE 8192                   // A: 16 m8-blocks x 4 k8-blocks x 128B
#define SB_STAGE 16384                  // B: 32 k-rows x 512B (swizzled 16B cols)
#define SB_BASE  (STAGES * SA_STAGE)                      // 32768
#define SG_BASE  (SB_BASE + STAGES * SB_STAGE)            // 98304
#define SMEM_BYTES (SG_BASE + BM * NE * 4)                // 102400

// ---------------- scratch ----------------
__device__ float  g_gates[NTOK * NE];                // softmax gates [N, E]
__device__ __half g_Wh[KTOT * OUT_DIM];              // fp16 We, [K, O] row-major, 16 MB

// ---------------- helpers ----------------
__device__ __forceinline__ uint32_t smem_u32(const void* p) {
    uint32_t a;
    asm("{ .reg .u64 t; cvta.to.shared.u64 t, %1; cvt.u32.u64 %0, t; }" : "=r"(a) : "l"(p));
    return a;
}
__device__ __forceinline__ uint32_t packh2(float lo, float hi) {
    uint32_t r;
    asm("cvt.rn.f16x2.f32 %0, %1, %2;" : "=r"(r) : "f"(hi), "f"(lo));
    return r;
}
// swizzled byte offset of 16B col-slot `col16` (0..31) in k-row `kr` of a B stage
__device__ __forceinline__ uint32_t bswz(int kr, int col16) {
    return (uint32_t)(kr * 512 + ((((col16 ^ kr) & 7) | (col16 & 24)) << 4));
}

// ---------------- kernel 1: gating softmax (32 tokens / 1024-thread block) ----------------
__global__ __launch_bounds__(1024) void gate_kernel(const float* __restrict__ x,
                                                    const float* __restrict__ Wg,
                                                    const float* __restrict__ bg) {
    __shared__ float sW[NE * IN_DIM];   // transposed: sW[e*1024 + i]
    int tid = threadIdx.x;
    for (int idx = tid; idx < NE * IN_DIM; idx += 1024) {
        int i = idx >> 3, e = idx & 7;
        sW[e * IN_DIM + i] = Wg[idx];
    }
    __syncthreads();
    int w = tid >> 5, lane = tid & 31;
    int n = blockIdx.x * 32 + w;
    float acc[NE];
#pragma unroll
    for (int e = 0; e < NE; e++) acc[e] = 0.f;
    const float* xr = x + (size_t)n * IN_DIM;
    for (int i = lane; i < IN_DIM; i += 32) {
        float xv = xr[i];
#pragma unroll
        for (int e = 0; e < NE; e++) acc[e] += xv * sW[e * IN_DIM + i];
    }
#pragma unroll
    for (int e = 0; e < NE; e++) {
#pragma unroll
        for (int off = 16; off; off >>= 1)
            acc[e] += __shfl_xor_sync(0xffffffffu, acc[e], off);
    }
    if (lane == 0) {
        float v[NE], m = -1e30f;
#pragma unroll
        for (int e = 0; e < NE; e++) { v[e] = acc[e] + bg[e]; m = fmaxf(m, v[e]); }
        float s = 0.f;
#pragma unroll
        for (int e = 0; e < NE; e++) { v[e] = expf(v[e] - m); s += v[e]; }
        float inv = 1.0f / s;
#pragma unroll
        for (int e = 0; e < NE; e++) g_gates[n * NE + e] = v[e] * inv;
    }
}

// ---------------- kernel 2: We fp32 -> fp16 copy (layout preserved) ----------------
__global__ __launch_bounds__(256) void convert_kernel(const float* __restrict__ We) {
    int total = KTOT * OUT_DIM / 8;
    for (int idx = blockIdx.x * blockDim.x + threadIdx.x; idx < total;
         idx += gridDim.x * blockDim.x) {
        const float4* s = (const float4*)We + (size_t)idx * 2;
        float4 a = s[0], b = s[1];
        uint4 w;
        w.x = packh2(a.x, a.y); w.y = packh2(a.z, a.w);
        w.z = packh2(b.x, b.y); w.w = packh2(b.z, b.w);
        *(uint4*)(g_Wh + (size_t)idx * 8) = w;
    }
}

// ---------------- kernel 3: fused fp16 mma GEMM, 128x256 CTA tile, 512 threads ----------------
__global__ __launch_bounds__(512, 1) void moe_mma_kernel(const float* __restrict__ x,
                                                         const float* __restrict__ be,
                                                         float* __restrict__ out) {
    extern __shared__ __align__(16) char smem[];
    const uint32_t aBase = smem_u32(smem);
    const uint32_t bBase = aBase + SB_BASE;
    float* sg = (float*)(smem + SG_BASE);

    int tid = threadIdx.x;
    int m0 = blockIdx.y * BM, o0 = blockIdx.x * BN;

    for (int i = tid; i < BM * NE; i += 512) sg[i] = g_gates[m0 * NE + i];
    __syncthreads();

    // ---- A producer mapping: 4 threads per row, one k8-quad each ----
    const int row = tid >> 2, qa = tid & 3;
    const int m8p = row >> 3, r8p = row & 7;
    const uint32_t aoffQ = (uint32_t)(((m8p * 4 + qa) * 128) + (((r8p + 4 * qa) & 7) * 16));
    const float* xrow = x + (size_t)(m0 + row) * IN_DIM;

    // ---- B producer mapping: 16 threads per k-row, 2 x 16B slots each ----
    const int kr = tid >> 4, segB = tid & 15;
    const uint32_t bd0 = bswz(kr, segB), bd1 = bswz(kr, segB + 16);

    auto produceB = [&](int st, int c) {
        uint32_t sbase = bBase + (uint32_t)st * SB_STAGE;
        if (c < 256) {
            int ic = c >> 3, e = c & 7;
            const __half* src = g_Wh + (size_t)(e * 1024 + ic * 32 + kr) * OUT_DIM + o0 + segB * 8;
            asm volatile("cp.async.cg.shared.global [%0], [%1], 16;" :: "r"(sbase + bd0), "l"(src));
            asm volatile("cp.async.cg.shared.global [%0], [%1], 16;" :: "r"(sbase + bd1), "l"(src + 128));
        } else {
            if (kr < 8) {
                const float* s0 = be + (size_t)kr * OUT_DIM + o0 + segB * 8;
                float4 a = *(const float4*)s0, b = *(const float4*)(s0 + 4);
                asm volatile("st.shared.v4.b32 [%0], {%1,%2,%3,%4};" :: "r"(sbase + bd0),
                             "r"(packh2(a.x, a.y)), "r"(packh2(a.z, a.w)),
                             "r"(packh2(b.x, b.y)), "r"(packh2(b.z, b.w)));
                a = *(const float4*)(s0 + 128); b = *(const float4*)(s0 + 132);
                asm volatile("st.shared.v4.b32 [%0], {%1,%2,%3,%4};" :: "r"(sbase + bd1),
                             "r"(packh2(a.x, a.y)), "r"(packh2(a.z, a.w)),
                             "r"(packh2(b.x, b.y)), "r"(packh2(b.z, b.w)));
            } else {
                asm volatile("st.shared.v4.b32 [%0], {%1,%1,%1,%1};" :: "r"(sbase + bd0), "r"(0u));
                asm volatile("st.shared.v4.b32 [%0], {%1,%1,%1,%1};" :: "r"(sbase + bd1), "r"(0u));
            }
        }
        asm volatile("cp.async.commit_group;");
    };
    auto produceA = [&](int st, int c) {
        uint32_t base = aBase + (uint32_t)st * SA_STAGE;
        if (c < 256) {
            int ic = c >> 3, e = c & 7;
            float ge = sg[row * NE + e];
            const float* p = xrow + ic * 32 + qa * 8;
            float4 v0 = *(const float4*)p, v1 = *(const float4*)(p + 4);
            asm volatile("st.shared.v4.b32 [%0], {%1,%2,%3,%4};" :: "r"(base + aoffQ),
                         "r"(packh2(v0.x * ge, v0.y * ge)), "r"(packh2(v0.z * ge, v0.w * ge)),
                         "r"(packh2(v1.x * ge, v1.y * ge)), "r"(packh2(v1.z * ge, v1.w * ge)));
        } else {
            if (qa == 0) {
                const float* g = &sg[row * NE];
                asm volatile("st.shared.v4.b32 [%0], {%1,%2,%3,%4};" :: "r"(base + aoffQ),
                             "r"(packh2(g[0], g[1])), "r"(packh2(g[2], g[3])),
                             "r"(packh2(g[4], g[5])), "r"(packh2(g[6], g[7])));
            } else {
                asm volatile("st.shared.v4.b32 [%0], {%1,%1,%1,%1};" :: "r"(base + aoffQ), "r"(0u));
            }
        }
    };

    // ---- accumulators / warp mapping (2m x 8n warps, 64x32 per warp) ----
    float acc[4][4][4];
#pragma unroll
    for (int mi = 0; mi < 4; mi++)
#pragma unroll
        for (int ni = 0; ni < 4; ni++)
#pragma unroll
            for (int q = 0; q < 4; q++) acc[mi][ni][q] = 0.f;

    int wid = tid >> 5, lane = tid & 31;
    int wm = (wid & 1) * 64, wn = (wid >> 1) * 32;
    int lr = lane >> 2, lc = lane & 3;
    const int wmBlk = (wid & 1) * 8;
    const int wn8 = (wid >> 1) * 4;               // col16 base

    // A ldmatrix lane constant
    const int jm = (lane >> 3) & 1, jk = lane >> 4, rr = lane & 7;
    const uint32_t aLane = (uint32_t)((jm * 4 + jk) * 128 + (((rr + 4 * jk) & 7) * 16));
    // B ldmatrix.trans lane constants
    const int jb = lane >> 3, rb = lane & 7;
    const int kb = 8 * (jb & 1) + rb;
    const int nb = jb >> 1;

    auto compute = [&](int st) {
        const uint32_t A = aBase + (uint32_t)st * SA_STAGE + aLane;
        const uint32_t B = bBase + (uint32_t)st * SB_STAGE;
#pragma unroll
        for (int ks = 0; ks < 2; ks++) {
            uint32_t bf[4][2];
#pragma unroll
            for (int p = 0; p < 2; p++) {
                int krL = 16 * ks + kb;
                int col16 = wn8 + 2 * p + nb;
                uint32_t addr = B + bswz(krL, col16);
                asm volatile("ldmatrix.sync.aligned.m8n8.x4.trans.shared.b16 {%0,%1,%2,%3}, [%4];"
                             : "=r"(bf[2 * p][0]), "=r"(bf[2 * p][1]),
                               "=r"(bf[2 * p + 1][0]), "=r"(bf[2 * p + 1][1])
                             : "r"(addr));
            }
#pragma unroll
            for (int mi = 0; mi < 4; mi++) {
                uint32_t a0, a1, a2, a3;
                uint32_t addr = A + (uint32_t)((((wmBlk + 2 * mi) * 4) + 2 * ks) * 128);
                asm volatile("ldmatrix.sync.aligned.m8n8.x4.shared.b16 {%0,%1,%2,%3}, [%4];"
                             : "=r"(a0), "=r"(a1), "=r"(a2), "=r"(a3) : "r"(addr));
#pragma unroll
                for (int ni = 0; ni < 4; ni++)
                    asm volatile(
                        "mma.sync.aligned.m16n8k16.row.col.f32.f16.f16.f32 "
                        "{%0,%1,%2,%3}, {%4,%5,%6,%7}, {%8,%9}, {%0,%1,%2,%3};"
                        : "+f"(acc[mi][ni][0]), "+f"(acc[mi][ni][1]),
                          "+f"(acc[mi][ni][2]), "+f"(acc[mi][ni][3])
                        : "r"(a0), "r"(a1), "r"(a2), "r"(a3),
                          "r"(bf[ni][0]), "r"(bf[ni][1]));
            }
        }
    };

    // ---- prologue: fill stages 0..2 ----
#pragma unroll
    for (int s = 0; s < STAGES - 1; s++) {
        produceA(s, s);
        produceB(s, s);
    }

    // ---- main loop: c = 0..253, produce chunk c+3 ----
    int st_c = 0, st_p = STAGES - 1;
#pragma unroll 1
    for (int c = 0; c < NCHUNK - STAGES + 1; c++) {
        asm volatile("cp.async.wait_group %0;" :: "n"(STAGES - 2) : "memory");
        __syncthreads();
        produceA(st_p, c + STAGES - 1);
        produceB(st_p, c + STAGES - 1);
        compute(st_c);
        st_c = (st_c == STAGES - 1) ? 0 : st_c + 1;
        st_p = (st_p == STAGES - 1) ? 0 : st_p + 1;
    }
    // ---- tail: last STAGES-1 chunks resident ----
    asm volatile("cp.async.wait_group 0;" ::: "memory");
    __syncthreads();
#pragma unroll
    for (int t = 0; t < STAGES - 1; t++) {
        compute(st_c);
        st_c = (st_c == STAGES - 1) ? 0 : st_c + 1;
    }

    // ---- epilogue: pure store (bias folded into GEMM) ----
#pragma unroll
    for (int mi = 0; mi < 4; mi++) {
        int r = m0 + wm + mi * 16 + lr;
#pragma unroll
        for (int ni = 0; ni < 4; ni++) {
            int cc = o0 + wn + ni * 8 + lc * 2;
            *(float2*)(out + (size_t)r * OUT_DIM + cc) =
                make_float2(acc[mi][ni][0], acc[mi][ni][1]);
            *(float2*)(out + (size_t)(r + 8) * OUT_DIM + cc) =
                make_float2(acc[mi][ni][2], acc[mi][ni][3]);
        }
    }
}

// ---------------- launch ----------------
extern "C" void kernel_launch(void* const* d_in, const int* in_sizes, int n_in,
                              void* d_out, int out_size) {
    const float* x  = (const float*)d_in[0];
    const float* We = (const float*)d_in[1];
    const float* be = (const float*)d_in[2];
    const float* Wg = (const float*)d_in[3];
    const float* bg = (const float*)d_in[4];
    float* out = (float*)d_out;

    cudaFuncSetAttribute(moe_mma_kernel, cudaFuncAttributeMaxDynamicSharedMemorySize, SMEM_BYTES);

    gate_kernel<<<NTOK / 32, 1024>>>(x, Wg, bg);
    convert_kernel<<<2048, 256>>>(We);
    moe_mma_kernel<<<dim3(OUT_DIM / BN, NTOK / BM), 512, SMEM_BYTES>>>(x, be, out);
}

// round 11
// speedup vs baseline: 2.1364x; 1.2584x over previous
#include <cuda_runtime.h>
#include <cuda_fp16.h>
#include <cstdint>
#include <math.h>

#define IN_DIM  1024
#define OUT_DIM 1024
#define NE      8
#define NTOK    8192
#define KTOT    (NE * IN_DIM)          // 8192
#define BM      128
#define BN      256
#define NCHUNK  129                     // 128 weight chunks (K=64) + 1 gate/bias chunk
#define STAGES  3

// SMEM per stage (bytes)
#define SA_STAGE 16384                  // A: 16 m8 x 8 k8 x 128B blocks
#define SB_STAGE 32768                  // B: 64 k-rows x 512B (swizzled 16B cols)
#define SB_BASE  (STAGES * SA_STAGE)                      // 49152
#define SG_BASE  (SB_BASE + STAGES * SB_STAGE)            // 147456
#define SMEM_BYTES (SG_BASE + BM * NE * 4)                // 151552

// ---------------- scratch ----------------
__device__ float  g_gates[NTOK * NE];                // softmax gates [N, E]
__device__ __half g_Wh[KTOT * OUT_DIM];              // fp16 We, [K, O] row-major, 16 MB

// ---------------- helpers ----------------
__device__ __forceinline__ uint32_t smem_u32(const void* p) {
    uint32_t a;
    asm("{ .reg .u64 t; cvta.to.shared.u64 t, %1; cvt.u32.u64 %0, t; }" : "=r"(a) : "l"(p));
    return a;
}
__device__ __forceinline__ uint32_t packh2(float lo, float hi) {
    uint32_t r;
    asm("cvt.rn.f16x2.f32 %0, %1, %2;" : "=r"(r) : "f"(hi), "f"(lo));
    return r;
}
// swizzled byte offset of 16B col-slot `col16` (0..31) in k-row `kr` (0..63) of a B stage
__device__ __forceinline__ uint32_t bswz(int kr, int col16) {
    return (uint32_t)(kr * 512 + ((((col16 ^ kr) & 7) | (col16 & 24)) << 4));
}

// ---------------- kernel 1: gating softmax ----------------
__global__ __launch_bounds__(1024) void gate_kernel(const float* __restrict__ x,
                                                    const float* __restrict__ Wg,
                                                    const float* __restrict__ bg) {
    __shared__ float sW[NE * IN_DIM];
    int tid = threadIdx.x;
    for (int idx = tid; idx < NE * IN_DIM; idx += 1024) {
        int i = idx >> 3, e = idx & 7;
        sW[e * IN_DIM + i] = Wg[idx];
    }
    __syncthreads();
    int w = tid >> 5, lane = tid & 31;
    int n = blockIdx.x * 32 + w;
    float acc[NE];
#pragma unroll
    for (int e = 0; e < NE; e++) acc[e] = 0.f;
    const float* xr = x + (size_t)n * IN_DIM;
    for (int i = lane; i < IN_DIM; i += 32) {
        float xv = xr[i];
#pragma unroll
        for (int e = 0; e < NE; e++) acc[e] += xv * sW[e * IN_DIM + i];
    }
#pragma unroll
    for (int e = 0; e < NE; e++) {
#pragma unroll
        for (int off = 16; off; off >>= 1)
            acc[e] += __shfl_xor_sync(0xffffffffu, acc[e], off);
    }
    if (lane == 0) {
        float v[NE], m = -1e30f;
#pragma unroll
        for (int e = 0; e < NE; e++) { v[e] = acc[e] + bg[e]; m = fmaxf(m, v[e]); }
        float s = 0.f;
#pragma unroll
        for (int e = 0; e < NE; e++) { v[e] = expf(v[e] - m); s += v[e]; }
        float inv = 1.0f / s;
#pragma unroll
        for (int e = 0; e < NE; e++) g_gates[n * NE + e] = v[e] * inv;
    }
}

// ---------------- kernel 2: We fp32 -> fp16 copy ----------------
__global__ __launch_bounds__(256) void convert_kernel(const float* __restrict__ We) {
    int total = KTOT * OUT_DIM / 8;
    for (int idx = blockIdx.x * blockDim.x + threadIdx.x; idx < total;
         idx += gridDim.x * blockDim.x) {
        const float4* s = (const float4*)We + (size_t)idx * 2;
        float4 a = s[0], b = s[1];
        uint4 w;
        w.x = packh2(a.x, a.y); w.y = packh2(a.z, a.w);
        w.z = packh2(b.x, b.y); w.w = packh2(b.z, b.w);
        *(uint4*)(g_Wh + (size_t)idx * 8) = w;
    }
}

// ---------------- kernel 3: fused fp16 mma GEMM, K=64 chunks ----------------
// Chunk c (<128): ic = c>>2 (x cols ic*32..+32), experts e0=2*(c&3), e0+1.
// A tile 128x64: k8 blocks 0..3 = e0-gated x, 4..7 = e1-gated x.
// Block (m8,k8) at (m8*8+k8)*128; row r8 at slot ((r8+4*k8)&7)*16.
__global__ __launch_bounds__(512, 1) void moe_mma_kernel(const float* __restrict__ x,
                                                         const float* __restrict__ be,
                                                         float* __restrict__ out) {
    extern __shared__ __align__(16) char smem[];
    const uint32_t aBase = smem_u32(smem);
    const uint32_t bBase = aBase + SB_BASE;
    float* sg = (float*)(smem + SG_BASE);

    int tid = threadIdx.x;
    int m0 = blockIdx.y * BM, o0 = blockIdx.x * BN;

    for (int i = tid; i < BM * NE; i += 512) sg[i] = g_gates[m0 * NE + i];
    __syncthreads();

    // ---- A producer mapping: 4 threads per row, quads k8=qa and k8=qa+4 ----
    const int row = tid >> 2, qa = tid & 3;
    const int m8p = row >> 3, r8p = row & 7;
    const uint32_t sw_row = (uint32_t)(((r8p + 4 * qa) & 7) * 16);   // same for qa and qa+4
    const uint32_t aoffQ0 = (uint32_t)((m8p * 8 + qa) * 128) + sw_row;
    const uint32_t aoffQ1 = (uint32_t)((m8p * 8 + qa + 4) * 128) + sw_row;
    const float* xrow = x + (size_t)(m0 + row) * IN_DIM;

    // x register cache: current and next 8 floats (one 32-col chunk / 4 threads)
    float4 xc0 = *(const float4*)(xrow + qa * 8);
    float4 xc1 = *(const float4*)(xrow + qa * 8 + 4);
    float4 xn0 = xc0, xn1 = xc1;

    // ---- B producer mapping: 8 threads per k-row, 4 x 16B slots ----
    const int kr = tid >> 3, segB = tid & 7;
    uint32_t bd[4];
#pragma unroll
    for (int j = 0; j < 4; j++) bd[j] = bswz(kr, segB + 8 * j);

    auto produceB = [&](int st, int cc) {
        uint32_t sbase = bBase + (uint32_t)st * SB_STAGE;
        if (cc < 128) {
            int ic = cc >> 2, t = cc & 3;
            int expert = 2 * t + (kr >> 5);
            const __half* src = g_Wh + (size_t)(expert * 1024 + ic * 32 + (kr & 31)) * OUT_DIM
                                + o0 + segB * 8;
#pragma unroll
            for (int j = 0; j < 4; j++)
                asm volatile("cp.async.cg.shared.global [%0], [%1], 16;"
                             :: "r"(sbase + bd[j]), "l"(src + 64 * j));
        } else {
            if (kr < 8) {
                const float* s0 = be + (size_t)kr * OUT_DIM + o0 + segB * 8;
#pragma unroll
                for (int j = 0; j < 4; j++) {
                    float4 a = *(const float4*)(s0 + 64 * j);
                    float4 b = *(const float4*)(s0 + 64 * j + 4);
                    asm volatile("st.shared.v4.b32 [%0], {%1,%2,%3,%4};" :: "r"(sbase + bd[j]),
                                 "r"(packh2(a.x, a.y)), "r"(packh2(a.z, a.w)),
                                 "r"(packh2(b.x, b.y)), "r"(packh2(b.z, b.w)));
                }
            } else {
#pragma unroll
                for (int j = 0; j < 4; j++)
                    asm volatile("st.shared.v4.b32 [%0], {%1,%1,%1,%1};" :: "r"(sbase + bd[j]), "r"(0u));
            }
        }
        asm volatile("cp.async.commit_group;");
    };
    auto produceA = [&](int st, int cc) {
        uint32_t base = aBase + (uint32_t)st * SA_STAGE;
        if (cc < 128) {
            int t = cc & 3, ic = cc >> 2;
            if (t == 0 && cc > 0) { xc0 = xn0; xc1 = xn1; }
            float ge0 = sg[row * NE + 2 * t];
            float ge1 = sg[row * NE + 2 * t + 1];
            asm volatile("st.shared.v4.b32 [%0], {%1,%2,%3,%4};" :: "r"(base + aoffQ0),
                         "r"(packh2(xc0.x * ge0, xc0.y * ge0)), "r"(packh2(xc0.z * ge0, xc0.w * ge0)),
                         "r"(packh2(xc1.x * ge0, xc1.y * ge0)), "r"(packh2(xc1.z * ge0, xc1.w * ge0)));
            asm volatile("st.shared.v4.b32 [%0], {%1,%2,%3,%4};" :: "r"(base + aoffQ1),
                         "r"(packh2(xc0.x * ge1, xc0.y * ge1)), "r"(packh2(xc0.z * ge1, xc0.w * ge1)),
                         "r"(packh2(xc1.x * ge1, xc1.y * ge1)), "r"(packh2(xc1.z * ge1, xc1.w * ge1)));
            if (t == 1 && ic < 31) {
                const float* p = xrow + (ic + 1) * 32 + qa * 8;
                xn0 = *(const float4*)p;
                xn1 = *(const float4*)(p + 4);
            }
        } else {
            if (qa == 0) {
                const float* g = &sg[row * NE];
                asm volatile("st.shared.v4.b32 [%0], {%1,%2,%3,%4};" :: "r"(base + aoffQ0),
                             "r"(packh2(g[0], g[1])), "r"(packh2(g[2], g[3])),
                             "r"(packh2(g[4], g[5])), "r"(packh2(g[6], g[7])));
            } else {
                asm volatile("st.shared.v4.b32 [%0], {%1,%1,%1,%1};" :: "r"(base + aoffQ0), "r"(0u));
            }
            asm volatile("st.shared.v4.b32 [%0], {%1,%1,%1,%1};" :: "r"(base + aoffQ1), "r"(0u));
        }
    };

    // ---- accumulators / warp mapping (2m x 8n warps, 64x32 per warp) ----
    float acc[4][4][4];
#pragma unroll
    for (int mi = 0; mi < 4; mi++)
#pragma unroll
        for (int ni = 0; ni < 4; ni++)
#pragma unroll
            for (int q = 0; q < 4; q++) acc[mi][ni][q] = 0.f;

    int wid = tid >> 5, lane = tid & 31;
    int wm = (wid & 1) * 64, wn = (wid >> 1) * 32;
    int lr = lane >> 2, lc = lane & 3;
    const int wmBlk = (wid & 1) * 8;
    const int wn8 = (wid >> 1) * 4;

    // A ldmatrix lane constant: jm = m8 offset, jk = k8 offset
    const int jm = (lane >> 3) & 1, jk = lane >> 4, rr = lane & 7;
    const uint32_t aLane = (uint32_t)(jm * 1024 + jk * 128 + (((rr + 4 * jk) & 7) * 16));
    // B ldmatrix.trans lane constants
    const int jb = lane >> 3, rb = lane & 7;
    const int kb = 8 * (jb & 1) + rb;
    const int nb = jb >> 1;

    auto compute = [&](int st) {
        const uint32_t A = aBase + (uint32_t)st * SA_STAGE + aLane;
        const uint32_t B = bBase + (uint32_t)st * SB_STAGE;
#pragma unroll
        for (int ks = 0; ks < 4; ks++) {
            uint32_t bf[4][2];
#pragma unroll
            for (int p = 0; p < 2; p++) {
                int krL = 16 * ks + kb;
                int col16 = wn8 + 2 * p + nb;
                uint32_t addr = B + bswz(krL, col16);
                asm volatile("ldmatrix.sync.aligned.m8n8.x4.trans.shared.b16 {%0,%1,%2,%3}, [%4];"
                             : "=r"(bf[2 * p][0]), "=r"(bf[2 * p][1]),
                               "=r"(bf[2 * p + 1][0]), "=r"(bf[2 * p + 1][1])
                             : "r"(addr));
            }
#pragma unroll
            for (int mi = 0; mi < 4; mi++) {
                uint32_t a0, a1, a2, a3;
                uint32_t addr = A + (uint32_t)((wmBlk + 2 * mi) * 1024 + ks * 256);
                asm volatile("ldmatrix.sync.aligned.m8n8.x4.shared.b16 {%0,%1,%2,%3}, [%4];"
                             : "=r"(a0), "=r"(a1), "=r"(a2), "=r"(a3) : "r"(addr));
#pragma unroll
                for (int ni = 0; ni < 4; ni++)
                    asm volatile(
                        "mma.sync.aligned.m16n8k16.row.col.f32.f16.f16.f32 "
                        "{%0,%1,%2,%3}, {%4,%5,%6,%7}, {%8,%9}, {%0,%1,%2,%3};"
                        : "+f"(acc[mi][ni][0]), "+f"(acc[mi][ni][1]),
                          "+f"(acc[mi][ni][2]), "+f"(acc[mi][ni][3])
                        : "r"(a0), "r"(a1), "r"(a2), "r"(a3),
                          "r"(bf[ni][0]), "r"(bf[ni][1]));
            }
        }
    };

    // ---- prologue: fill stages 0, 1 ----
#pragma unroll
    for (int s = 0; s < STAGES - 1; s++) {
        produceA(s, s);
        produceB(s, s);
    }

    // ---- main loop: c = 0..126, produce chunk c+2 ----
    int st_c = 0, st_p = STAGES - 1;
#pragma unroll 1
    for (int c = 0; c < NCHUNK - STAGES + 1; c++) {
        asm volatile("cp.async.wait_group %0;" :: "n"(STAGES - 2) : "memory");
        __syncthreads();
        produceA(st_p, c + STAGES - 1);
        produceB(st_p, c + STAGES - 1);
        compute(st_c);
        st_c = (st_c == STAGES - 1) ? 0 : st_c + 1;
        st_p = (st_p == STAGES - 1) ? 0 : st_p + 1;
    }
    // ---- tail: last STAGES-1 chunks resident ----
    asm volatile("cp.async.wait_group 0;" ::: "memory");
    __syncthreads();
#pragma unroll
    for (int t = 0; t < STAGES - 1; t++) {
        compute(st_c);
        st_c = (st_c == STAGES - 1) ? 0 : st_c + 1;
    }

    // ---- epilogue: pure store (bias folded into GEMM) ----
#pragma unroll
    for (int mi = 0; mi < 4; mi++) {
        int r = m0 + wm + mi * 16 + lr;
#pragma unroll
        for (int ni = 0; ni < 4; ni++) {
            int cc = o0 + wn + ni * 8 + lc * 2;
            *(float2*)(out + (size_t)r * OUT_DIM + cc) =
                make_float2(acc[mi][ni][0], acc[mi][ni][1]);
            *(float2*)(out + (size_t)(r + 8) * OUT_DIM + cc) =
                make_float2(acc[mi][ni][2], acc[mi][ni][3]);
        }
    }
}

// ---------------- launch ----------------
extern "C" void kernel_launch(void* const* d_in, const int* in_sizes, int n_in,
                              void* d_out, int out_size) {
    const float* x  = (const float*)d_in[0];
    const float* We = (const float*)d_in[1];
    const float* be = (const float*)d_in[2];
    const float* Wg = (const float*)d_in[3];
    const float* bg = (const float*)d_in[4];
    float* out = (float*)d_out;

    cudaFuncSetAttribute(moe_mma_kernel, cudaFuncAttributeMaxDynamicSharedMemorySize, SMEM_BYTES);

    gate_kernel<<<NTOK / 32, 1024>>>(x, Wg, bg);
    convert_kernel<<<2048, 256>>>(We);
    moe_mma_kernel<<<dim3(OUT_DIM / BN, NTOK / BM), 512, SMEM_BYTES>>>(x, be, out);
}